// round 6
// baseline (speedup 1.0000x reference)
#include <cuda_runtime.h>
#include <cstdint>

#define KVOL 27
#define CIN  64
#define COUT 64
#define BM   128

// Set by detect_kmap_dtype: 1 if kmap buffer is int64, 0 if int32.
__device__ int g_kmap_is64;

__global__ void detect_kmap_dtype(const unsigned int* __restrict__ km) {
    // If the buffer is int64 (values < 2^31, little-endian), every odd 32-bit
    // word is the zero high-half. If it is int32, odd words are random indices
    // in [0, n_pts) and are ~never all zero across 64 samples.
    int all_zero = 1;
    #pragma unroll 1
    for (int i = 0; i < 64; ++i) {
        if (km[2 * i + 1] != 0u) { all_zero = 0; break; }
    }
    g_kmap_is64 = all_zero;
}

// round-to-nearest fp32 -> tf32 (keeps result in a b32 reg)
__device__ __forceinline__ uint32_t cvt_tf32(float x) {
    uint32_t u;
    asm("cvt.rna.tf32.f32 %0, %1;" : "=r"(u) : "f"(x));
    return u;
}

__device__ __forceinline__ void mma_tf32(float c[4], const uint32_t a[4], const uint32_t b[2]) {
    asm volatile(
        "mma.sync.aligned.m16n8k8.row.col.f32.tf32.tf32.f32 "
        "{%0,%1,%2,%3}, {%4,%5,%6,%7}, {%8,%9}, {%0,%1,%2,%3};\n"
        : "+f"(c[0]), "+f"(c[1]), "+f"(c[2]), "+f"(c[3])
        : "r"(a[0]), "r"(a[1]), "r"(a[2]), "r"(a[3]),
          "r"(b[0]), "r"(b[1]));
}

// XOR swizzles: conflict-free for the m16n8k8 fragment access patterns.
// A: 32 lanes read (row=g..g+7 twice, col=c..c+3) -> bank = (col ^ 4*(row&7)) % 32, all distinct.
__device__ __forceinline__ int a_off(int row, int col) {
    return row * 64 + (col ^ ((row & 7) << 2));
}
// B: 32 lanes read (k=t4..t4+3, co = 8 values) -> bank = (co ^ 8*(ci&3)) % 32, all distinct.
__device__ __forceinline__ int b_off(int ci, int co) {
    return ci * 64 + (co ^ ((ci & 3) << 3));
}

__global__ __launch_bounds__(128, 4)
void sparse_conv_tf32(const float* __restrict__ features,
                      const float* __restrict__ wkernel,
                      const long long* __restrict__ kmap64,
                      const int* __restrict__ kmap32,
                      const int* __restrict__ kmask,
                      float* __restrict__ out,
                      int n_pts)
{
    __shared__ float As[BM * 64];   // 32 KB, tf32 bit patterns, swizzled
    __shared__ float Bs[64 * 64];   // 16 KB, tf32 bit patterns, swizzled

    const int tid  = threadIdx.x;          // 0..127
    const int lane = tid & 31;
    const int warp = tid >> 5;             // 0..3  (M dimension)
    const int m0   = warp * 32;
    const int g    = lane >> 2;            // 0..7
    const int t4   = lane & 3;             // 0..3
    const long long blk0 = (long long)blockIdx.x * BM;
    const int is64 = g_kmap_is64;

    float acc[2][8][4];
    #pragma unroll
    for (int mi = 0; mi < 2; ++mi)
        #pragma unroll
        for (int ni = 0; ni < 8; ++ni)
            #pragma unroll
            for (int j = 0; j < 4; ++j)
                acc[mi][ni][j] = 0.0f;

    for (int k = 0; k < KVOL; ++k) {
        // ---- stage W[k] (64x64 fp32) into Bs as tf32 ----
        {
            const int ci  = tid >> 1;             // 0..63
            const int cob = (tid & 1) * 32;       // 0 or 32
            const float4* src =
                reinterpret_cast<const float4*>(wkernel + ((k * 64 + ci) * 64 + cob));
            #pragma unroll
            for (int j = 0; j < 8; ++j) {
                float4 v = src[j];
                uint4 w;
                w.x = cvt_tf32(v.x); w.y = cvt_tf32(v.y);
                w.z = cvt_tf32(v.z); w.w = cvt_tf32(v.w);
                *reinterpret_cast<uint4*>(Bs + b_off(ci, cob + j * 4)) = w;
            }
        }
        // ---- gather A tile (128 x 64): one thread per point ----
        {
            const long long pt = blk0 + tid;
            int m = 0;
            const float4* src = nullptr;
            if (pt < n_pts) {
                const long long e = pt * KVOL + k;
                m = kmask[e];
                if (m) {
                    long long idx = is64 ? kmap64[e] : (long long)kmap32[e];
                    // defensive clamp: a bad index becomes a wrong value,
                    // never an illegal access
                    if (idx < 0 || idx >= n_pts) idx = 0;
                    src = reinterpret_cast<const float4*>(features + idx * CIN);
                }
            }
            if (m) {
                #pragma unroll
                for (int j = 0; j < 16; ++j) {
                    float4 v = src[j];
                    uint4 w;
                    w.x = cvt_tf32(v.x); w.y = cvt_tf32(v.y);
                    w.z = cvt_tf32(v.z); w.w = cvt_tf32(v.w);
                    *reinterpret_cast<uint4*>(As + a_off(tid, j * 4)) = w;
                }
            } else {
                const uint4 z = make_uint4(0u, 0u, 0u, 0u);
                #pragma unroll
                for (int j = 0; j < 16; ++j)
                    *reinterpret_cast<uint4*>(As + a_off(tid, j * 4)) = z;
            }
        }
        __syncthreads();

        // ---- warp tile 32(M) x 64(N), K=64 in 8 slices of 8 ----
        #pragma unroll
        for (int ks = 0; ks < 8; ++ks) {
            const int kb = ks * 8;
            uint32_t a[2][4];
            #pragma unroll
            for (int mi = 0; mi < 2; ++mi) {
                const int row = m0 + mi * 16 + g;
                const int col = kb + t4;
                a[mi][0] = __float_as_uint(As[a_off(row,     col)]);
                a[mi][1] = __float_as_uint(As[a_off(row + 8, col)]);
                a[mi][2] = __float_as_uint(As[a_off(row,     col + 4)]);
                a[mi][3] = __float_as_uint(As[a_off(row + 8, col + 4)]);
            }
            uint32_t b[8][2];
            #pragma unroll
            for (int ni = 0; ni < 8; ++ni) {
                const int kr = kb + t4;
                const int co = ni * 8 + g;
                b[ni][0] = __float_as_uint(Bs[b_off(kr,     co)]);
                b[ni][1] = __float_as_uint(Bs[b_off(kr + 4, co)]);
            }
            #pragma unroll
            for (int mi = 0; mi < 2; ++mi)
                #pragma unroll
                for (int ni = 0; ni < 8; ++ni)
                    mma_tf32(acc[mi][ni], a[mi], b[ni]);
        }
        __syncthreads();
    }

    // ---- epilogue: c frag layout -> out[n, co] (fp32) ----
    #pragma unroll
    for (int mi = 0; mi < 2; ++mi) {
        const long long r0 = blk0 + m0 + mi * 16 + g;
        #pragma unroll
        for (int ni = 0; ni < 8; ++ni) {
            const int col = ni * 8 + t4 * 2;
            if (r0 < n_pts)
                *reinterpret_cast<float2*>(out + r0 * COUT + col) =
                    make_float2(acc[mi][ni][0], acc[mi][ni][1]);
            if (r0 + 8 < n_pts)
                *reinterpret_cast<float2*>(out + (r0 + 8) * COUT + col) =
                    make_float2(acc[mi][ni][2], acc[mi][ni][3]);
        }
    }
}

extern "C" void kernel_launch(void* const* d_in, const int* in_sizes, int n_in,
                              void* d_out, int out_size) {
    const float* features = (const float*)d_in[0];
    const float* wkernel  = (const float*)d_in[1];
    const void*  kmap     = d_in[2];
    const int*   kmask    = (const int*)d_in[3];
    float*       out      = (float*)d_out;

    const int n_pts = in_sizes[0] / CIN;
    const int grid  = (n_pts + BM - 1) / BM;

    detect_kmap_dtype<<<1, 1>>>((const unsigned int*)kmap);
    sparse_conv_tf32<<<grid, 128>>>(features, wkernel,
                                    (const long long*)kmap,
                                    (const int*)kmap,
                                    kmask, out, n_pts);
}